// round 9
// baseline (speedup 1.0000x reference)
#include <cuda_runtime.h>
#include <cstdint>
#include <cstddef>

#define VOCAB   32000
#define HID     768
#define HS1_N   128
#define TILE_M  128
#define NCHUNK  24          // 768 / 32, divisible by 3 for the unroll
#define NTILES  512         // 65536 / 128

// ---------------- shared memory layout (bytes) ----------------
// 3 stage pairs. Stage buf b: A at b*STAGE_PAIR, B at +STAGE_BYTES.
// Row stride 36 floats (32 data + 4 pad) -> conflict-free fragment LDS.
#define STAGE_BYTES 18432u              // 128 * 36 * 4
#define STAGE_PAIR  36864u
#define SM_B1       110592u             // 3 * STAGE_PAIR
#define SM_W2       111104u
#define SMEM_TOTAL  111616u
// Epilogue h-matrix reuses stage area: 128 * 132 * 4 = 67584 <= 110592.

static __device__ __forceinline__ void cp16(uint32_t dst, const void* src) {
    asm volatile("cp.async.cg.shared.global [%0], [%1], 16;" :: "r"(dst), "l"(src));
}

static __device__ __forceinline__ uint32_t smem_u32(const void* p) {
    uint32_t a;
    asm("{ .reg .u64 t; cvta.to.shared.u64 t, %1; cvt.u32.u64 %0, t; }" : "=r"(a) : "l"(p));
    return a;
}

static __device__ __forceinline__ void mma_tf32(float* d, const uint32_t* a,
                                                uint32_t b0, uint32_t b1) {
    asm volatile(
        "mma.sync.aligned.m16n8k8.row.col.f32.tf32.tf32.f32 "
        "{%0,%1,%2,%3}, {%4,%5,%6,%7}, {%8,%9}, {%0,%1,%2,%3};"
        : "+f"(d[0]), "+f"(d[1]), "+f"(d[2]), "+f"(d[3])
        : "r"(a[0]), "r"(a[1]), "r"(a[2]), "r"(a[3]), "r"(b0), "r"(b1));
}

// ---------------- device scratch (no dynamic alloc allowed) ----------------
__device__ float g_B[NCHUNK * 4096];   // W1h transposed [chunk][n(128)][k(32)], tf32-RN rounded
__device__ int   g_tk64;               // 1 if tk buffer is int64, 0 if int32

// ---------------- staging kernel ----------------
__global__ void stage_kernel(const float* __restrict__ W1, const int* __restrict__ tk32) {
    int idx = blockIdx.x * blockDim.x + threadIdx.x;
    if (idx < NCHUNK * 4096) {
        int c = idx >> 12;            // chunk
        int k = (idx >> 7) & 31;      // k within chunk
        int n = idx & 127;            // output col -> coalesced W1 read
        float v = W1[(size_t)(VOCAB + c * 32 + k) * HS1_N + n];
        float r;
        asm("cvt.rna.tf32.f32 %0, %1;" : "=f"(r) : "f"(v));   // RN to tf32 (unbiased)
        g_B[c * 4096 + n * 32 + k] = r;
    }
    if (idx == 0) {
        // int64 tk => odd 32-bit words all zero (tokens < 2^15)
        int z = 0;
        for (int i = 1; i < 32; i += 2) z |= tk32[i];
        g_tk64 = (z == 0) ? 1 : 0;
    }
}

// ---------------- main kernel helpers ----------------
static __device__ __forceinline__ void load_stage(uint32_t sb, uint32_t buf_off, int c,
                                                  int tid, const float* __restrict__ atile) {
    uint32_t abase = sb + buf_off;
    uint32_t bbase = abase + STAGE_BYTES;
    const float* bsrc = g_B + c * 4096;
#pragma unroll
    for (int q = 0; q < 4; q++) {
        int o = q * 256 + tid;        // 0..1023 float4 index
        int m = o >> 3, j = o & 7;    // row, 16B-group
        uint32_t doff = (uint32_t)(m * 36 + j * 4) * 4u;   // padded row stride
        cp16(abase + doff, atile + (size_t)m * HID + c * 32 + j * 4);
        cp16(bbase + doff, bsrc + o * 4);                  // g_B is linear per chunk
    }
    asm volatile("cp.async.commit_group;" ::: "memory");
}

static __device__ __forceinline__ void compute_stage(const char* smem, uint32_t buf_off,
                                                     float acc[2][8][4],
                                                     int wm, int wn, int lr, int lc) {
    const uint32_t* As = (const uint32_t*)(smem + buf_off);
    const uint32_t* Bs = (const uint32_t*)(smem + buf_off + STAGE_BYTES);
#pragma unroll
    for (int s = 0; s < 4; s++) {
        int k0 = s * 8 + lc;
        uint32_t a[2][4];
#pragma unroll
        for (int mt = 0; mt < 2; mt++) {
            int r = wm * 32 + mt * 16 + lr;
            a[mt][0] = As[r * 36 + k0];
            a[mt][1] = As[(r + 8) * 36 + k0];
            a[mt][2] = As[r * 36 + k0 + 4];
            a[mt][3] = As[(r + 8) * 36 + k0 + 4];
        }
#pragma unroll
        for (int nt = 0; nt < 8; nt++) {
            int n = wn * 64 + nt * 8 + lr;
            uint32_t b0  = Bs[n * 36 + k0];
            uint32_t b1f = Bs[n * 36 + k0 + 4];
            mma_tf32(acc[0][nt], a[0], b0, b1f);
            mma_tf32(acc[1][nt], a[1], b0, b1f);
        }
    }
}

__global__ __launch_bounds__(256, 2)
void classifier_kernel(const void* __restrict__ tk_raw,
                       const float* __restrict__ hs0,
                       const float* __restrict__ W1,
                       const float* __restrict__ b1,
                       const float* __restrict__ W2,
                       const float* __restrict__ b2,
                       float* __restrict__ out) {
    extern __shared__ char smem[];
    uint32_t sb = smem_u32(smem);
    int tid  = threadIdx.x;
    int warp = tid >> 5, lane = tid & 31;
    int lr = lane >> 2, lc = lane & 3;
    int wm = warp >> 1;               // 0..3  -> 32-row band
    int wn = warp & 1;                // 0..1  -> 64-col band
    int tile = blockIdx.x;

    if (tid < 128)  ((float*)(smem + SM_B1))[tid]       = b1[tid];
    else            ((float*)(smem + SM_W2))[tid - 128] = W2[tid - 128];

    const float* atile = hs0 + (size_t)tile * TILE_M * HID;

    // Prefetch the epilogue token index early (hides the int64 branch + LDG).
    int row  = tid >> 1;
    int half = tid & 1;
    long long tok;
    if (g_tk64) tok = ((const long long*)tk_raw)[tile * TILE_M + row];
    else        tok = (long long)((const int*)tk_raw)[tile * TILE_M + row];

    float acc[2][8][4];
#pragma unroll
    for (int mt = 0; mt < 2; mt++)
#pragma unroll
        for (int nt = 0; nt < 8; nt++)
#pragma unroll
            for (int e = 0; e < 4; e++) acc[mt][nt][e] = 0.0f;

    // prologue: stages 0 and 1 in flight
    load_stage(sb, 0u,          0, tid, atile);
    load_stage(sb, STAGE_PAIR,  1, tid, atile);

    // Main loop, 3x unrolled so stage offsets are compile-time constants.
    // Per chunk c: wait until stage c resident (<=1 younger group pending),
    // one barrier (also proves all warps finished chunk c-1, so its buffer
    // (c+2)%3 is reusable), refill, compute.
#pragma unroll 1
    for (int cc = 0; cc < NCHUNK; cc += 3) {
#pragma unroll
        for (int u = 0; u < 3; u++) {
            int c = cc + u;
            asm volatile("cp.async.wait_group 1;" ::: "memory");
            __syncthreads();
            if (c + 2 < NCHUNK)
                load_stage(sb, (uint32_t)(((u + 2) % 3) * STAGE_PAIR), c + 2, tid, atile);
            else
                asm volatile("cp.async.commit_group;" ::: "memory");  // keep group count in step
            compute_stage(smem, (uint32_t)(u * STAGE_PAIR), acc, wm, wn, lr, lc);
        }
    }
    __syncthreads();   // all MMA reads done before stage area is reused

    // ---------------- epilogue ----------------
    // Dump acc -> SMEM h matrix [128][132] (reuses stage area).
    float* hs = (float*)smem;
#pragma unroll
    for (int mt = 0; mt < 2; mt++) {
#pragma unroll
        for (int nt = 0; nt < 8; nt++) {
            int r  = wm * 32 + mt * 16 + lr;
            int ccol = wn * 64 + nt * 8 + lc * 2;
            *(float2*)&hs[r * 132 + ccol]       = make_float2(acc[mt][nt][0], acc[mt][nt][1]);
            *(float2*)&hs[(r + 8) * 132 + ccol] = make_float2(acc[mt][nt][2], acc[mt][nt][3]);
        }
    }
    __syncthreads();

    // Each pair of threads finishes one token: gather W1[tok] + b1, relu, dot W2.
    const float4* trow = (const float4*)(W1 + (size_t)tok * HS1_N + half * 64);
    const float*  b1h  = ((const float*)(smem + SM_B1)) + half * 64;
    const float*  w2h  = ((const float*)(smem + SM_W2)) + half * 64;
    const float*  hrow = hs + row * 132 + half * 64;

    float sum = 0.0f;
#pragma unroll
    for (int jq = 0; jq < 16; jq++) {
        float4 t4 = trow[jq];
        const float* tv = &t4.x;
#pragma unroll
        for (int e = 0; e < 4; e++) {
            int j = jq * 4 + e;
            float v = hrow[j] + tv[e] + b1h[j];
            sum = fmaf(fmaxf(v, 0.0f), w2h[j], sum);
        }
    }
    // The two half-sums sit in adjacent lanes: reduce with one shuffle.
    sum += __shfl_down_sync(0xFFFFFFFFu, sum, 1);
    if (half == 0)
        out[tile * TILE_M + row] = sum + b2[0];
}

// ---------------- launch ----------------
extern "C" void kernel_launch(void* const* d_in, const int* in_sizes, int n_in,
                              void* d_out, int out_size) {
    const void*  tk  = d_in[0];                   // int64 or int32 (auto-detected)
    const float* hs0 = (const float*)d_in[1];     // [16,4096,768]
    const float* W1  = (const float*)d_in[2];     // [32768,128]
    const float* b1  = (const float*)d_in[3];     // [128]
    const float* W2  = (const float*)d_in[4];     // [128]
    const float* b2  = (const float*)d_in[5];     // [1]
    float* out = (float*)d_out;                   // [65536]

    cudaFuncSetAttribute(classifier_kernel,
                         cudaFuncAttributeMaxDynamicSharedMemorySize, SMEM_TOTAL);

    stage_kernel<<<(NCHUNK * 4096 + 255) / 256, 256>>>(W1, (const int*)tk);
    classifier_kernel<<<NTILES, 256, SMEM_TOTAL>>>(tk, hs0, W1, b1, W2, b2, out);
}

// round 10
// speedup vs baseline: 1.1099x; 1.1099x over previous
#include <cuda_runtime.h>
#include <cstdint>
#include <cstddef>

#define VOCAB   32000
#define HID     768
#define HS1_N   128
#define TILE_M  128
#define NCHUNK  24          // 768 / 32
#define NTILES  512         // 65536 / 128

// ---------------- shared memory layout (bytes) ----------------
// Row stride 40 floats (32 data + 8 pad):
//  - LDS.32 (A frags): bank = lr*8 + lc, conflict-free
//  - LDS.64 (B frags): bank-pair = lr*8 + lc*2, conflict-free per phase
#define ROWW        40u
#define STAGE_BYTES 20480u              // 128 * 40 * 4
#define STAGE_PAIR  40960u              // A + B
#define SM_B1       81920u              // 2 * STAGE_PAIR
#define SM_W2       82432u
#define SMEM_TOTAL  82944u
// Epilogue h-matrix reuses stage area: 128 * 132 * 4 = 67584 <= 81920.

static __device__ __forceinline__ void cp16(uint32_t dst, const void* src) {
    asm volatile("cp.async.cg.shared.global [%0], [%1], 16;" :: "r"(dst), "l"(src));
}

static __device__ __forceinline__ uint32_t smem_u32(const void* p) {
    uint32_t a;
    asm("{ .reg .u64 t; cvta.to.shared.u64 t, %1; cvt.u32.u64 %0, t; }" : "=r"(a) : "l"(p));
    return a;
}

static __device__ __forceinline__ void mma_tf32(float* d, const uint32_t* a,
                                                uint32_t b0, uint32_t b1) {
    asm volatile(
        "mma.sync.aligned.m16n8k8.row.col.f32.tf32.tf32.f32 "
        "{%0,%1,%2,%3}, {%4,%5,%6,%7}, {%8,%9}, {%0,%1,%2,%3};"
        : "+f"(d[0]), "+f"(d[1]), "+f"(d[2]), "+f"(d[3])
        : "r"(a[0]), "r"(a[1]), "r"(a[2]), "r"(a[3]), "r"(b0), "r"(b1));
}

// ---------------- device scratch (no dynamic alloc allowed) ----------------
// g_B layout: [chunk][n(128)][p(32)] where position p = s*8 + lc*2 + h holds
// original k-within-chunk = s*8 + lc + 4*h. This makes each thread's MMA
// B-fragment pair (k0, k0+4) adjacent -> one LDS.64.
__device__ float g_B[NCHUNK * 4096];
__device__ int   g_tk64;               // 1 if tk buffer is int64, 0 if int32

// ---------------- staging kernel ----------------
__global__ void stage_kernel(const float* __restrict__ W1, const int* __restrict__ tk32) {
    int idx = blockIdx.x * blockDim.x + threadIdx.x;
    if (idx < NCHUNK * 4096) {
        int c    = idx >> 12;          // chunk
        int kpos = (idx >> 7) & 31;    // source k within chunk (coalesced W1 read)
        int n    = idx & 127;          // output col
        float v = W1[(size_t)(VOCAB + c * 32 + kpos) * HS1_N + n];
        float r;
        asm("cvt.rna.tf32.f32 %0, %1;" : "=f"(r) : "f"(v));   // RN to tf32 (unbiased)
        int s = kpos >> 3, j = kpos & 7;
        int p = s * 8 + (j & 3) * 2 + (j >> 2);               // fragment-pair permute
        g_B[c * 4096 + n * 32 + p] = r;
    }
    if (idx == 0) {
        // int64 tk => odd 32-bit words all zero (tokens < 2^15)
        int z = 0;
        for (int i = 1; i < 32; i += 2) z |= tk32[i];
        g_tk64 = (z == 0) ? 1 : 0;
    }
}

// ---------------- main kernel helpers ----------------
static __device__ __forceinline__ void load_stage(uint32_t sb, int buf, int c, int tid,
                                                  const float* __restrict__ atile) {
    uint32_t abase = sb + (uint32_t)buf * STAGE_PAIR;
    uint32_t bbase = abase + STAGE_BYTES;
    const float* bsrc = g_B + c * 4096;
#pragma unroll
    for (int q = 0; q < 4; q++) {
        int o = q * 256 + tid;        // 0..1023 float4 index
        int m = o >> 3, j = o & 7;    // row, 16B-group
        uint32_t doff = (uint32_t)(m * ROWW + j * 4) * 4u;   // padded row stride
        cp16(abase + doff, atile + (size_t)m * HID + c * 32 + j * 4);
        cp16(bbase + doff, bsrc + o * 4);                    // byte copy keeps permute
    }
    asm volatile("cp.async.commit_group;" ::: "memory");
}

__global__ __launch_bounds__(256, 2)
void classifier_kernel(const void* __restrict__ tk_raw,
                       const float* __restrict__ hs0,
                       const float* __restrict__ W1,
                       const float* __restrict__ b1,
                       const float* __restrict__ W2,
                       const float* __restrict__ b2,
                       float* __restrict__ out) {
    extern __shared__ char smem[];
    uint32_t sb = smem_u32(smem);
    int tid  = threadIdx.x;
    int warp = tid >> 5, lane = tid & 31;
    int lr = lane >> 2, lc = lane & 3;
    int wm = warp >> 1;               // 0..3  -> 32-row band
    int wn = warp & 1;                // 0..1  -> 64-col band
    int tile = blockIdx.x;

    if (tid < 128)  ((float*)(smem + SM_B1))[tid]       = b1[tid];
    else            ((float*)(smem + SM_W2))[tid - 128] = W2[tid - 128];

    const float* atile = hs0 + (size_t)tile * TILE_M * HID;

    // Prefetch the epilogue token index early.
    int row  = tid >> 1;
    int half = tid & 1;
    long long tok;
    if (g_tk64) tok = ((const long long*)tk_raw)[tile * TILE_M + row];
    else        tok = (long long)((const int*)tk_raw)[tile * TILE_M + row];

    float acc[2][8][4];
#pragma unroll
    for (int mt = 0; mt < 2; mt++)
#pragma unroll
        for (int nt = 0; nt < 8; nt++)
#pragma unroll
            for (int e = 0; e < 4; e++) acc[mt][nt][e] = 0.0f;

    // prologue
    load_stage(sb, 0, 0, tid, atile);

    for (int c = 0; c < NCHUNK; c++) {
        int buf = c & 1;
        if (c + 1 < NCHUNK) {
            load_stage(sb, (c + 1) & 1, c + 1, tid, atile);
            asm volatile("cp.async.wait_group 1;" ::: "memory");
        } else {
            asm volatile("cp.async.wait_group 0;" ::: "memory");
        }
        __syncthreads();

        const uint32_t* As = (const uint32_t*)(smem + buf * STAGE_PAIR);
        const uint32_t* Bs = (const uint32_t*)(smem + buf * STAGE_PAIR + STAGE_BYTES);

#pragma unroll
        for (int s = 0; s < 4; s++) {
            int k0 = s * 8 + lc;
            uint32_t a[2][4];
#pragma unroll
            for (int mt = 0; mt < 2; mt++) {
                int r = wm * 32 + mt * 16 + lr;
                a[mt][0] = As[r * ROWW + k0];
                a[mt][1] = As[(r + 8) * ROWW + k0];
                a[mt][2] = As[r * ROWW + k0 + 4];
                a[mt][3] = As[(r + 8) * ROWW + k0 + 4];
            }
#pragma unroll
            for (int nt = 0; nt < 8; nt++) {
                int n = wn * 64 + nt * 8 + lr;
                // permuted layout: both k-halves adjacent -> single LDS.64
                uint2 bb = *(const uint2*)&Bs[n * ROWW + s * 8 + lc * 2];
                mma_tf32(acc[0][nt], a[0], bb.x, bb.y);
                mma_tf32(acc[1][nt], a[1], bb.x, bb.y);
            }
        }
        __syncthreads();   // protect buf before refill next iteration
    }

    // ---------------- epilogue ----------------
    // Dump acc -> SMEM h matrix [128][132] (reuses stage area).
    float* hs = (float*)smem;
#pragma unroll
    for (int mt = 0; mt < 2; mt++) {
#pragma unroll
        for (int nt = 0; nt < 8; nt++) {
            int r  = wm * 32 + mt * 16 + lr;
            int cc = wn * 64 + nt * 8 + lc * 2;
            *(float2*)&hs[r * 132 + cc]       = make_float2(acc[mt][nt][0], acc[mt][nt][1]);
            *(float2*)&hs[(r + 8) * 132 + cc] = make_float2(acc[mt][nt][2], acc[mt][nt][3]);
        }
    }
    __syncthreads();

    // Each pair of threads finishes one token: gather W1[tok] + b1, relu, dot W2.
    const float4* trow = (const float4*)(W1 + (size_t)tok * HS1_N + half * 64);
    const float*  b1h  = ((const float*)(smem + SM_B1)) + half * 64;
    const float*  w2h  = ((const float*)(smem + SM_W2)) + half * 64;
    const float*  hrow = hs + row * 132 + half * 64;

    float sum = 0.0f;
#pragma unroll
    for (int jq = 0; jq < 16; jq++) {
        float4 t4 = trow[jq];
        const float* tv = &t4.x;
#pragma unroll
        for (int e = 0; e < 4; e++) {
            int j = jq * 4 + e;
            float v = hrow[j] + tv[e] + b1h[j];
            sum = fmaf(fmaxf(v, 0.0f), w2h[j], sum);
        }
    }
    // Two half-sums sit in adjacent lanes: one shuffle finishes the token.
    sum += __shfl_down_sync(0xFFFFFFFFu, sum, 1);
    if (half == 0)
        out[tile * TILE_M + row] = sum + b2[0];
}

// ---------------- launch ----------------
extern "C" void kernel_launch(void* const* d_in, const int* in_sizes, int n_in,
                              void* d_out, int out_size) {
    const void*  tk  = d_in[0];                   // int64 or int32 (auto-detected)
    const float* hs0 = (const float*)d_in[1];     // [16,4096,768]
    const float* W1  = (const float*)d_in[2];     // [32768,128]
    const float* b1  = (const float*)d_in[3];     // [128]
    const float* W2  = (const float*)d_in[4];     // [128]
    const float* b2  = (const float*)d_in[5];     // [1]
    float* out = (float*)d_out;                   // [65536]

    cudaFuncSetAttribute(classifier_kernel,
                         cudaFuncAttributeMaxDynamicSharedMemorySize, SMEM_TOTAL);

    stage_kernel<<<(NCHUNK * 4096 + 255) / 256, 256>>>(W1, (const int*)tk);
    classifier_kernel<<<NTILES, 256, SMEM_TOTAL>>>(tk, hs0, W1, b1, W2, b2, out);
}

// round 13
// speedup vs baseline: 1.3568x; 1.2225x over previous
#include <cuda_runtime.h>
#include <cuda_fp16.h>
#include <cstdint>
#include <cstddef>

#define VOCAB   32000
#define HID     768
#define HS1_N   128
#define TILE_M  128
#define NCHUNK  24          // 768 / 32
#define NTILES  512         // 65536 / 128

// ---------------- shared memory layout (bytes) ----------------
// A stage: 128 rows x 40 f32 (32 data + 8 pad) = 20480 B
//   fp16-frag pair loads: LDS.64 banks (4*lr + lc) -> conflict-free
// B stage: 128 rows x 40 half (32 data + 8 pad) = 10240 B
//   permuted pairs: LDS.64 banks (10*lr + lc) -> <=2/bank (LDS.64 floor)
#define AROWW       40u                 // f32 per A row
#define BROWW       40u                 // half per B row
#define A_BYTES     20480u
#define B_BYTES     10240u
#define STAGE_PAIR  30720u
#define SM_B1       67584u              // after epilogue hs matrix 128*132*4
#define SM_W2       68096u
#define SMEM_TOTAL  68608u
// Stage bufs occupy [0, 61440); epilogue hs reuses [0, 67584).

static __device__ __forceinline__ void cp16(uint32_t dst, const void* src) {
    asm volatile("cp.async.cg.shared.global [%0], [%1], 16;" :: "r"(dst), "l"(src));
}

static __device__ __forceinline__ uint32_t smem_u32(const void* p) {
    uint32_t a;
    asm("{ .reg .u64 t; cvta.to.shared.u64 t, %1; cvt.u32.u64 %0, t; }" : "=r"(a) : "l"(p));
    return a;
}

// pack two f32 -> f16x2 (RN). PTX: first source -> high half, second -> low.
static __device__ __forceinline__ uint32_t pack_h2(float lo, float hi) {
    uint32_t r;
    asm("cvt.rn.f16x2.f32 %0, %1, %2;" : "=r"(r) : "f"(hi), "f"(lo));
    return r;
}

static __device__ __forceinline__ void mma_f16(float* d, const uint32_t* a,
                                               uint32_t b0, uint32_t b1) {
    asm volatile(
        "mma.sync.aligned.m16n8k16.row.col.f32.f16.f16.f32 "
        "{%0,%1,%2,%3}, {%4,%5,%6,%7}, {%8,%9}, {%0,%1,%2,%3};"
        : "+f"(d[0]), "+f"(d[1]), "+f"(d[2]), "+f"(d[3])
        : "r"(a[0]), "r"(a[1]), "r"(a[2]), "r"(a[3]), "r"(b0), "r"(b1));
}

// ---------------- device scratch (no dynamic alloc allowed) ----------------
// g_Bh layout: [chunk][n(128)][pos(32)] halves. Within a chunk, original
// k = s*16 + t4*2 + ps*8 + h  is stored at  pos = s*16 + t4*4 + ps*2 + h,
// so each thread's (b0,b1) fragment = 4 adjacent halves -> one LDS.64.
__device__ __half g_Bh[NCHUNK * 4096];
__device__ int    g_tk64;              // 1 if tk buffer is int64, 0 if int32

// ---------------- staging kernel ----------------
__global__ void stage_kernel(const float* __restrict__ W1, const int* __restrict__ tk32) {
    int idx = blockIdx.x * blockDim.x + threadIdx.x;
    if (idx < NCHUNK * 4096) {
        int c = idx >> 12;             // chunk
        int k = (idx >> 7) & 31;       // source k within chunk (coalesced W1 read)
        int n = idx & 127;             // output col
        float v = W1[(size_t)(VOCAB + c * 32 + k) * HS1_N + n];
        int s  = k >> 4, r = k & 15;
        int ps = r >> 3, q = r & 7;
        int t4 = q >> 1, h = q & 1;
        int pos = s * 16 + t4 * 4 + ps * 2 + h;
        g_Bh[c * 4096 + n * 32 + pos] = __float2half_rn(v);
    }
    if (idx == 0) {
        // int64 tk => odd 32-bit words all zero (tokens < 2^15)
        int z = 0;
        for (int i = 1; i < 32; i += 2) z |= tk32[i];
        g_tk64 = (z == 0) ? 1 : 0;
    }
}

// ---------------- main kernel helpers ----------------
static __device__ __forceinline__ void load_stage(uint32_t sb, int buf, int c, int tid,
                                                  const float* __restrict__ atile) {
    uint32_t abase = sb + (uint32_t)buf * STAGE_PAIR;
    uint32_t bbase = abase + A_BYTES;
    // A: 128 x 32 f32 = 1024 x 16B granules
#pragma unroll
    for (int q = 0; q < 4; q++) {
        int o = q * 256 + tid;
        int m = o >> 3, j = o & 7;
        cp16(abase + (uint32_t)(m * 160 + j * 16),
             atile + (size_t)m * HID + c * 32 + j * 4);
    }
    // B: 128 x 32 half = 512 x 16B granules (permuted source, byte copy)
    const char* bsrc = (const char*)g_Bh + (size_t)c * 8192;
#pragma unroll
    for (int q = 0; q < 2; q++) {
        int o = q * 256 + tid;
        int n = o >> 2, g = o & 3;
        cp16(bbase + (uint32_t)(n * 80 + g * 16), bsrc + o * 16);
    }
    asm volatile("cp.async.commit_group;" ::: "memory");
}

__global__ __launch_bounds__(256, 2)
void classifier_kernel(const void* __restrict__ tk_raw,
                       const float* __restrict__ hs0,
                       const float* __restrict__ W1,
                       const float* __restrict__ b1,
                       const float* __restrict__ W2,
                       const float* __restrict__ b2,
                       float* __restrict__ out) {
    extern __shared__ char smem[];
    uint32_t sb = smem_u32(smem);
    int tid  = threadIdx.x;
    int warp = tid >> 5, lane = tid & 31;
    int lr = lane >> 2, lc = lane & 3;
    int wm = warp >> 1;               // 0..3  -> 32-row band
    int wn = warp & 1;                // 0..1  -> 64-col band
    int tile = blockIdx.x;

    if (tid < 128)  ((float*)(smem + SM_B1))[tid]       = b1[tid];
    else            ((float*)(smem + SM_W2))[tid - 128] = W2[tid - 128];

    const float* atile = hs0 + (size_t)tile * TILE_M * HID;

    // Prefetch the epilogue token index early.
    int row  = tid >> 1;
    int half = tid & 1;
    long long tok;
    if (g_tk64) tok = ((const long long*)tk_raw)[tile * TILE_M + row];
    else        tok = (long long)((const int*)tk_raw)[tile * TILE_M + row];

    float acc[2][8][4];
#pragma unroll
    for (int mt = 0; mt < 2; mt++)
#pragma unroll
        for (int nt = 0; nt < 8; nt++)
#pragma unroll
            for (int e = 0; e < 4; e++) acc[mt][nt][e] = 0.0f;

    // prologue
    load_stage(sb, 0, 0, tid, atile);

    for (int c = 0; c < NCHUNK; c++) {
        int buf = c & 1;
        if (c + 1 < NCHUNK) {
            load_stage(sb, (c + 1) & 1, c + 1, tid, atile);
            asm volatile("cp.async.wait_group 1;" ::: "memory");
        } else {
            asm volatile("cp.async.wait_group 0;" ::: "memory");
        }
        __syncthreads();

        const float*    As = (const float*)(smem + buf * STAGE_PAIR);
        const uint32_t* Bs = (const uint32_t*)(smem + buf * STAGE_PAIR + A_BYTES);

#pragma unroll
        for (int s = 0; s < 2; s++) {        // two k16 steps per 32-chunk
            uint32_t a[2][4];
#pragma unroll
            for (int mt = 0; mt < 2; mt++) {
                int r = wm * 32 + mt * 16 + lr;
                int base = s * 16 + lc * 2;
                float2 p0 = *(const float2*)&As[r * AROWW + base];
                float2 p1 = *(const float2*)&As[(r + 8) * AROWW + base];
                float2 p2 = *(const float2*)&As[r * AROWW + base + 8];
                float2 p3 = *(const float2*)&As[(r + 8) * AROWW + base + 8];
                a[mt][0] = pack_h2(p0.x, p0.y);
                a[mt][1] = pack_h2(p1.x, p1.y);
                a[mt][2] = pack_h2(p2.x, p2.y);
                a[mt][3] = pack_h2(p3.x, p3.y);
            }
#pragma unroll
            for (int nt = 0; nt < 8; nt++) {
                int n = wn * 64 + nt * 8 + lr;
                // permuted fp16 layout: (b0,b1) adjacent -> single LDS.64
                uint2 bb = *(const uint2*)&Bs[n * (BROWW / 2) + s * 8 + lc * 2];
                mma_f16(acc[0][nt], a[0], bb.x, bb.y);
                mma_f16(acc[1][nt], a[1], bb.x, bb.y);
            }
        }
        __syncthreads();   // protect buf before refill next iteration
    }

    // ---------------- epilogue ----------------
    // Dump acc -> SMEM h matrix [128][132] (reuses stage area).
    float* hs = (float*)smem;
#pragma unroll
    for (int mt = 0; mt < 2; mt++) {
#pragma unroll
        for (int nt = 0; nt < 8; nt++) {
            int r  = wm * 32 + mt * 16 + lr;
            int cc = wn * 64 + nt * 8 + lc * 2;
            *(float2*)&hs[r * 132 + cc]       = make_float2(acc[mt][nt][0], acc[mt][nt][1]);
            *(float2*)&hs[(r + 8) * 132 + cc] = make_float2(acc[mt][nt][2], acc[mt][nt][3]);
        }
    }
    __syncthreads();

    // Each pair of threads finishes one token: gather W1[tok] + b1, relu, dot W2.
    const float4* trow = (const float4*)(W1 + (size_t)tok * HS1_N + half * 64);
    const float*  b1h  = ((const float*)(smem + SM_B1)) + half * 64;
    const float*  w2h  = ((const float*)(smem + SM_W2)) + half * 64;
    const float*  hrow = hs + row * 132 + half * 64;

    float sum = 0.0f;
#pragma unroll
    for (int jq = 0; jq < 16; jq++) {
        float4 t4 = trow[jq];
        const float* tv = &t4.x;
#pragma unroll
        for (int e = 0; e < 4; e++) {
            int j = jq * 4 + e;
            float v = hrow[j] + tv[e] + b1h[j];
            sum = fmaf(fmaxf(v, 0.0f), w2h[j], sum);
        }
    }
    // Two half-sums sit in adjacent lanes: one shuffle finishes the token.
    sum += __shfl_down_sync(0xFFFFFFFFu, sum, 1);
    if (half == 0)
        out[tile * TILE_M + row] = sum + b2[0];
}

// ---------------- launch ----------------
extern "C" void kernel_launch(void* const* d_in, const int* in_sizes, int n_in,
                              void* d_out, int out_size) {
    const void*  tk  = d_in[0];                   // int64 or int32 (auto-detected)
    const float* hs0 = (const float*)d_in[1];     // [16,4096,768]
    const float* W1  = (const float*)d_in[2];     // [32768,128]
    const float* b1  = (const float*)d_in[3];     // [128]
    const float* W2  = (const float*)d_in[4];     // [128]
    const float* b2  = (const float*)d_in[5];     // [1]
    float* out = (float*)d_out;                   // [65536]

    cudaFuncSetAttribute(classifier_kernel,
                         cudaFuncAttributeMaxDynamicSharedMemorySize, SMEM_TOTAL);

    stage_kernel<<<(NCHUNK * 4096 + 255) / 256, 256>>>(W1, (const int*)tk);
    classifier_kernel<<<NTILES, 256, SMEM_TOTAL>>>(tk, hs0, W1, b1, W2, b2, out);
}

// round 17
// speedup vs baseline: 1.4892x; 1.0976x over previous
#include <cuda_runtime.h>
#include <cuda_fp16.h>
#include <cstdint>
#include <cstddef>

#define VOCAB   32000
#define HID     768
#define HS1_N   128
#define TILE_M  64          // smaller CTA -> 4 CTAs/SM -> independent pipelines
#define NCHUNK  24          // 768 / 32
#define NTILES  1024        // 65536 / 64

// ---------------- shared memory layout (bytes) ----------------
// A stage: 64 rows x 40 f32 (32 data + 8 pad) = 10240 B
// B stage: 128 rows x 40 half (32 data + 8 pad) = 10240 B
#define AROWW       40u                 // f32 per A row
#define A_BYTES     10240u
#define STAGE_PAIR  20480u
#define SM_B1       40960u              // 2 * STAGE_PAIR
#define SM_W2       41472u
#define SMEM_TOTAL  41984u
// Epilogue hs matrix reuses stage area: 64 * 132 * 4 = 33792 <= 40960.

static __device__ __forceinline__ void cp16(uint32_t dst, const void* src) {
    asm volatile("cp.async.cg.shared.global [%0], [%1], 16;" :: "r"(dst), "l"(src));
}

static __device__ __forceinline__ uint32_t smem_u32(const void* p) {
    uint32_t a;
    asm("{ .reg .u64 t; cvta.to.shared.u64 t, %1; cvt.u32.u64 %0, t; }" : "=r"(a) : "l"(p));
    return a;
}

// pack two f32 -> f16x2 (RN). PTX: first source -> high half, second -> low.
static __device__ __forceinline__ uint32_t pack_h2(float lo, float hi) {
    uint32_t r;
    asm("cvt.rn.f16x2.f32 %0, %1, %2;" : "=r"(r) : "f"(hi), "f"(lo));
    return r;
}

static __device__ __forceinline__ void mma_f16(float* d, const uint32_t* a,
                                               uint32_t b0, uint32_t b1) {
    asm volatile(
        "mma.sync.aligned.m16n8k16.row.col.f32.f16.f16.f32 "
        "{%0,%1,%2,%3}, {%4,%5,%6,%7}, {%8,%9}, {%0,%1,%2,%3};"
        : "+f"(d[0]), "+f"(d[1]), "+f"(d[2]), "+f"(d[3])
        : "r"(a[0]), "r"(a[1]), "r"(a[2]), "r"(a[3]), "r"(b0), "r"(b1));
}

// ---------------- device scratch (no dynamic alloc allowed) ----------------
// g_Bh layout: [chunk][n(128)][pos(32)] halves, fragment-pair permuted so each
// thread's (b0,b1) = 4 adjacent halves -> one LDS.64.
__device__ __half g_Bh[NCHUNK * 4096];
__device__ int    g_tk64;              // 1 if tk buffer is int64, 0 if int32

// ---------------- staging kernel ----------------
__global__ void stage_kernel(const float* __restrict__ W1, const int* __restrict__ tk32) {
    int idx = blockIdx.x * blockDim.x + threadIdx.x;
    if (idx < NCHUNK * 4096) {
        int c = idx >> 12;             // chunk
        int k = (idx >> 7) & 31;       // source k within chunk (coalesced W1 read)
        int n = idx & 127;             // output col
        float v = W1[(size_t)(VOCAB + c * 32 + k) * HS1_N + n];
        int s  = k >> 4, r = k & 15;
        int ps = r >> 3, q = r & 7;
        int t4 = q >> 1, h = q & 1;
        int pos = s * 16 + t4 * 4 + ps * 2 + h;
        g_Bh[c * 4096 + n * 32 + pos] = __float2half_rn(v);
    }
    if (idx == 0) {
        // int64 tk => odd 32-bit words all zero (tokens < 2^15)
        int z = 0;
        for (int i = 1; i < 32; i += 2) z |= tk32[i];
        g_tk64 = (z == 0) ? 1 : 0;
    }
}

// ---------------- main kernel helpers ----------------
static __device__ __forceinline__ void load_stage(uint32_t sb, int buf, int c, int tid,
                                                  const float* __restrict__ atile) {
    uint32_t abase = sb + (uint32_t)buf * STAGE_PAIR;
    uint32_t bbase = abase + A_BYTES;
    // A: 64 x 32 f32 = 512 x 16B granules, 128 threads -> 4 iters
#pragma unroll
    for (int q = 0; q < 4; q++) {
        int o = q * 128 + tid;
        int m = o >> 3, j = o & 7;
        cp16(abase + (uint32_t)(m * 160 + j * 16),
             atile + (size_t)m * HID + c * 32 + j * 4);
    }
    // B: 128 x 32 half = 512 x 16B granules (permuted source, byte copy)
    const char* bsrc = (const char*)g_Bh + (size_t)c * 8192;
#pragma unroll
    for (int q = 0; q < 4; q++) {
        int o = q * 128 + tid;
        int n = o >> 2, g = o & 3;
        cp16(bbase + (uint32_t)(n * 80 + g * 16), bsrc + o * 16);
    }
    asm volatile("cp.async.commit_group;" ::: "memory");
}

__global__ __launch_bounds__(128, 4)
void classifier_kernel(const void* __restrict__ tk_raw,
                       const float* __restrict__ hs0,
                       const float* __restrict__ W1,
                       const float* __restrict__ b1,
                       const float* __restrict__ W2,
                       const float* __restrict__ b2,
                       float* __restrict__ out) {
    extern __shared__ char smem[];
    uint32_t sb = smem_u32(smem);
    int tid  = threadIdx.x;
    int warp = tid >> 5, lane = tid & 31;
    int lr = lane >> 2, lc = lane & 3;
    int wm = warp >> 1;               // 0..1  -> 32-row band
    int wn = warp & 1;                // 0..1  -> 64-col band
    int tile = blockIdx.x;

    if (tid < 128) ((float*)(smem + SM_B1))[tid] = b1[tid];
    ((float*)(smem + SM_W2))[tid] = W2[tid];

    const float* atile = hs0 + (size_t)tile * TILE_M * HID;

    // Prefetch the epilogue token index early.
    int row  = tid >> 1;              // 0..63
    int half = tid & 1;
    long long tok;
    if (g_tk64) tok = ((const long long*)tk_raw)[tile * TILE_M + row];
    else        tok = (long long)((const int*)tk_raw)[tile * TILE_M + row];

    float acc[2][8][4];
#pragma unroll
    for (int mt = 0; mt < 2; mt++)
#pragma unroll
        for (int nt = 0; nt < 8; nt++)
#pragma unroll
            for (int e = 0; e < 4; e++) acc[mt][nt][e] = 0.0f;

    // prologue
    load_stage(sb, 0, 0, tid, atile);

    for (int c = 0; c < NCHUNK; c++) {
        int buf = c & 1;
        if (c + 1 < NCHUNK) {
            load_stage(sb, (c + 1) & 1, c + 1, tid, atile);
            asm volatile("cp.async.wait_group 1;" ::: "memory");
        } else {
            asm volatile("cp.async.wait_group 0;" ::: "memory");
        }
        __syncthreads();

        const float*    As = (const float*)(smem + buf * STAGE_PAIR);
        const uint32_t* Bs = (const uint32_t*)(smem + buf * STAGE_PAIR + A_BYTES);

#pragma unroll
        for (int s = 0; s < 2; s++) {        // two k16 steps per 32-chunk
            uint32_t a[2][4];
#pragma unroll
            for (int mt = 0; mt < 2; mt++) {
                int r = wm * 32 + mt * 16 + lr;
                int base = s * 16 + lc * 2;
                float2 p0 = *(const float2*)&As[r * AROWW + base];
                float2 p1 = *(const float2*)&As[(r + 8) * AROWW + base];
                float2 p2 = *(const float2*)&As[r * AROWW + base + 8];
                float2 p3 = *(const float2*)&As[(r + 8) * AROWW + base + 8];
                a[mt][0] = pack_h2(p0.x, p0.y);
                a[mt][1] = pack_h2(p1.x, p1.y);
                a[mt][2] = pack_h2(p2.x, p2.y);
                a[mt][3] = pack_h2(p3.x, p3.y);
            }
#pragma unroll
            for (int nt = 0; nt < 8; nt++) {
                int n = wn * 64 + nt * 8 + lr;
                // permuted fp16 layout: (b0,b1) adjacent -> single LDS.64
                uint2 bb = *(const uint2*)&Bs[n * 20 + s * 8 + lc * 2];
                mma_f16(acc[0][nt], a[0], bb.x, bb.y);
                mma_f16(acc[1][nt], a[1], bb.x, bb.y);
            }
        }
        __syncthreads();   // protect buf before refill next iteration
    }

    // ---------------- epilogue ----------------
    // Dump acc -> SMEM h matrix [64][132] (reuses stage area).
    float* hs = (float*)smem;
#pragma unroll
    for (int mt = 0; mt < 2; mt++) {
#pragma unroll
        for (int nt = 0; nt < 8; nt++) {
            int r  = wm * 32 + mt * 16 + lr;
            int cc = wn * 64 + nt * 8 + lc * 2;
            *(float2*)&hs[r * 132 + cc]       = make_float2(acc[mt][nt][0], acc[mt][nt][1]);
            *(float2*)&hs[(r + 8) * 132 + cc] = make_float2(acc[mt][nt][2], acc[mt][nt][3]);
        }
    }
    __syncthreads();

    // Each pair of threads finishes one token: gather W1[tok] + b1, relu, dot W2.
    const float4* trow = (const float4*)(W1 + (size_t)tok * HS1_N + half * 64);
    const float*  b1h  = ((const float*)(smem + SM_B1)) + half * 64;
    const float*  w2h  = ((const float*)(smem + SM_W2)) + half * 64;
    const float*  hrow = hs + row * 132 + half * 64;

    float sum = 0.0f;
#pragma unroll
    for (int jq = 0; jq < 16; jq++) {
        float4 t4 = trow[jq];
        const float* tv = &t4.x;
#pragma unroll
        for (int e = 0; e < 4; e++) {
            int j = jq * 4 + e;
            float v = hrow[j] + tv[e] + b1h[j];
            sum = fmaf(fmaxf(v, 0.0f), w2h[j], sum);
        }
    }
    // Two half-sums sit in adjacent lanes: one shuffle finishes the token.
    sum += __shfl_down_sync(0xFFFFFFFFu, sum, 1);
    if (half == 0)
        out[tile * TILE_M + row] = sum + b2[0];
}

// ---------------- launch ----------------
extern "C" void kernel_launch(void* const* d_in, const int* in_sizes, int n_in,
                              void* d_out, int out_size) {
    const void*  tk  = d_in[0];                   // int64 or int32 (auto-detected)
    const float* hs0 = (const float*)d_in[1];     // [16,4096,768]
    const float* W1  = (const float*)d_in[2];     // [32768,128]
    const float* b1  = (const float*)d_in[3];     // [128]
    const float* W2  = (const float*)d_in[4];     // [128]
    const float* b2  = (const float*)d_in[5];     // [1]
    float* out = (float*)d_out;                   // [65536]

    cudaFuncSetAttribute(classifier_kernel,
                         cudaFuncAttributeMaxDynamicSharedMemorySize, SMEM_TOTAL);

    stage_kernel<<<(NCHUNK * 4096 + 255) / 256, 256>>>(W1, (const int*)tk);
    classifier_kernel<<<NTILES, 128, SMEM_TOTAL>>>(tk, hs0, W1, b1, W2, b2, out);
}